// round 16
// baseline (speedup 1.0000x reference)
#include <cuda_runtime.h>
#include <cstdint>
#include <cstddef>

typedef unsigned long long ull;

// device scratch (allocs forbidden)
__device__ float g_qh[64 * 1024];
__device__ float g_ws[64 * 1024 * 16];                 // [b][d][h]
__device__ float g_scores_part[4][64 * 16 * 2048];     // [dq][b][h][s]
__device__ float g_attn[64 * 2048 * 16];               // [b][s][h]
__device__ float g_vbar[64 * 16 * 1024];               // [b][h][d] (RED.ADD target)
__device__ float g_concat[64 * 1024];
__device__ float g_outpre[64 * 1024];

__device__ __forceinline__ ull pk2(float x, float y) {
    ull r; asm("mov.b64 %0, {%1,%2};" : "=l"(r) : "f"(x), "f"(y)); return r;
}
__device__ __forceinline__ void upk2(float& x, float& y, ull v) {
    asm("mov.b64 {%0,%1}, %2;" : "=f"(x), "=f"(y) : "l"(v));
}
__device__ __forceinline__ ull fma2(ull a, ull b, ull c) {
    ull d; asm("fma.rn.f32x2 %0, %1, %2, %3;" : "=l"(d) : "l"(a), "l"(b), "l"(c)); return d;
}
__device__ __forceinline__ ull add2(ull a, ull b) {
    ull c; asm("add.rn.f32x2 %0, %1, %2;" : "=l"(c) : "l"(a), "l"(b)); return c;
}
__device__ __forceinline__ unsigned smem_u32(const void* p) {
    return (unsigned)__cvta_generic_to_shared(p);
}
__device__ __forceinline__ void cpa16(unsigned s, const void* g) {
    asm volatile("cp.async.cg.shared.global [%0], [%1], 16;" :: "r"(s), "l"(g));
}
__device__ __forceinline__ void cpa_commit() {
    asm volatile("cp.async.commit_group;" ::: "memory");
}
template <int N> __device__ __forceinline__ void cpa_wait() {
    asm volatile("cp.async.wait_group %0;" :: "n"(N) : "memory");
}

__global__ __launch_bounds__(256) void k_init(const float* __restrict__ bq,
                                              const float* __restrict__ bv,
                                              const float* __restrict__ bo) {
    int i = blockIdx.x * 256 + threadIdx.x;   // 65536 threads
    int c = i & 1023;
    g_qh[i] = bq[c]; g_concat[i] = bv[c]; g_outpre[i] = bo[c];
    // zero g_vbar (1M floats = 256K float4; 4 per thread)
    float4 z; z.x = 0.f; z.y = 0.f; z.z = 0.f; z.w = 0.f;
    float4* vb = (float4*)g_vbar;
    #pragma unroll
    for (int j = 0; j < 4; j++) vb[i + j * 65536] = z;
}

// C[64,1024] += A[64,1024] @ W[1024,1024]; 16-way k-split over by, 64-col tiles over bx.
// mode 0: A=q -> g_qh | mode 1: A=g_vbar head-sliced (h=bx) -> g_concat
// mode 2: A=g_concat -> g_outpre
__global__ __launch_bounds__(256) void gemm_ksplit(const float* __restrict__ Ain,
                                                   const float* __restrict__ W, int mode) {
    __shared__ float As[64 * 68];
    __shared__ float Wsm[64 * 64];
    int bx = blockIdx.x, by = blockIdx.y, tid = threadIdx.x;
    int col0 = bx * 64, db = by * 64;

    if (mode == 1) {
        for (int idx = tid; idx < 4096; idx += 256) {
            int bb = idx >> 6, dd = idx & 63;
            As[bb * 68 + dd] = g_vbar[(size_t)bb * 16384 + (size_t)bx * 1024 + db + dd];
        }
    } else {
        const float* A = (mode == 0) ? Ain : g_concat;
        for (int idx = tid; idx < 4096; idx += 256) {
            int bb = idx >> 6, dd = idx & 63;
            As[bb * 68 + dd] = A[(size_t)bb * 1024 + db + dd];
        }
    }
    for (int idx = tid; idx < 4096; idx += 256) {
        int dd = idx >> 6, j = idx & 63;
        Wsm[dd * 64 + j] = W[(size_t)(db + dd) * 1024 + col0 + j];
    }
    __syncthreads();

    int tj = tid & 15, tb = tid >> 4;
    float acc[4][4] = {};
    const float4* Ws4 = (const float4*)Wsm;
    #pragma unroll 8
    for (int dd = 0; dd < 64; dd++) {
        float4 w = Ws4[dd * 16 + tj];
        #pragma unroll
        for (int bb = 0; bb < 4; bb++) {
            float a = As[(tb * 4 + bb) * 68 + dd];
            acc[bb][0] = fmaf(a, w.x, acc[bb][0]);
            acc[bb][1] = fmaf(a, w.y, acc[bb][1]);
            acc[bb][2] = fmaf(a, w.z, acc[bb][2]);
            acc[bb][3] = fmaf(a, w.w, acc[bb][3]);
        }
    }
    float* C = (mode == 0) ? g_qh : (mode == 1) ? g_concat : g_outpre;
    #pragma unroll
    for (int bb = 0; bb < 4; bb++)
        #pragma unroll
        for (int jj = 0; jj < 4; jj++)
            atomicAdd(&C[(size_t)(tb * 4 + bb) * 1024 + col0 + tj * 4 + jj], acc[bb][jj]);
}

// g_ws[b][d][h] = 0.125 * sum_j Wk[d, 64h+j] * g_qh[b, 64h+j]; grid (16 dt, 8 bt, 4 hz)
// (R13-exact; the load-once variant measured neutral/worse.)
__global__ __launch_bounds__(256) void k_ws(const float* __restrict__ Wk) {
    __shared__ float Wks[64 * 68];
    __shared__ float qhs[8 * 64];
    int dt = blockIdx.x, bt = blockIdx.y, hz = blockIdx.z, tid = threadIdx.x;
    int td = tid & 63, tg = tid >> 6;
    for (int hi = 0; hi < 4; hi++) {
        int h = hz * 4 + hi;
        __syncthreads();
        for (int idx = tid; idx < 4096; idx += 256) {
            int dd = idx >> 6, j = idx & 63;
            Wks[dd * 68 + j] = Wk[(size_t)(dt * 64 + dd) * 1024 + h * 64 + j];
        }
        for (int idx = tid; idx < 512; idx += 256) {
            int bb = idx >> 6, j = idx & 63;
            qhs[bb * 64 + j] = g_qh[(size_t)(bt * 8 + bb) * 1024 + h * 64 + j];
        }
        __syncthreads();
        float a0 = 0.f, a1 = 0.f;
        #pragma unroll
        for (int j4 = 0; j4 < 16; j4++) {
            float4 w  = *(const float4*)&Wks[td * 68 + j4 * 4];
            float4 qa = *(const float4*)&qhs[(tg * 2 + 0) * 64 + j4 * 4];
            float4 qb = *(const float4*)&qhs[(tg * 2 + 1) * 64 + j4 * 4];
            a0 = fmaf(w.x, qa.x, fmaf(w.y, qa.y, fmaf(w.z, qa.z, fmaf(w.w, qa.w, a0))));
            a1 = fmaf(w.x, qb.x, fmaf(w.y, qb.y, fmaf(w.z, qb.z, fmaf(w.w, qb.w, a1))));
        }
        int d = dt * 64 + td;
        g_ws[((size_t)(bt * 8 + tg * 2 + 0) * 1024 + d) * 16 + h] = a0 * 0.125f;
        g_ws[((size_t)(bt * 8 + tg * 2 + 1) * 1024 + d) * 16 + h] = a1 * 0.125f;
    }
}

// ---------------- pass 1: stream k -> partial scores ----------------
// grid (64 b, 16 st, 4 dq). CTA tile: 128 s x 256 d, 8 chunks of 32 d.
// 3-stage cp.async ring (stage = [128 rows][9 f4]), fully unrolled.
// Thread (hg=tid>>7, dg=(tid>>5)&3, r=tid&31): 4 rows, 8 heads, 8 d/chunk.
// dyn smem = 16384 + 3*18432 = 71680 B; 3 CTAs/SM.  (R13-exact.)
__global__ __launch_bounds__(256, 3) void k_scores(const float* __restrict__ k) {
    extern __shared__ float sm[];
    float* ws_s = sm;                          // 4096 f: [256 d][16 h]
    float4* pipe = (float4*)(sm + 4096);       // 3 stages x 1152 f4
    const int b = blockIdx.x, st = blockIdx.y, dq = blockIdx.z;
    const int tid = threadIdx.x;
    const int r = tid & 31;
    const int dg = (tid >> 5) & 3;
    const int hg = tid >> 7;

    {   // stage ws slice (coalesced)
        const float4* src = (const float4*)(g_ws + (size_t)b * 16384 + dq * 4096);
        float4* dst = (float4*)ws_s;
        #pragma unroll
        for (int i = 0; i < 4; i++) dst[tid + i * 256] = src[tid + i * 256];
    }

    const float4* k4 = (const float4*)k;
    const size_t gbase = ((size_t)b * 2048 + st * 128) * 256 + dq * 64;   // f4 units
    const int row0 = tid >> 3, col0 = tid & 7;
    const float4* kg = k4 + gbase + (size_t)row0 * 256 + col0;
    const unsigned sbase = smem_u32(pipe);
    const unsigned soff = sbase + (unsigned)(row0 * 9 + col0) * 16u;

#define KS_ISSUE(c) do { \
    unsigned sb = soff + (unsigned)(((c) % 3) * 1152) * 16u; \
    _Pragma("unroll") \
    for (int i = 0; i < 4; i++) \
        cpa16(sb + (unsigned)i * (32u * 9u * 16u), \
              kg + (size_t)i * 32 * 256 + (c) * 8); \
} while (0)

    KS_ISSUE(0); cpa_commit();
    KS_ISSUE(1); cpa_commit();

    ull acc[4][4];   // [row i][h-pair p within hg]
    #pragma unroll
    for (int i = 0; i < 4; i++)
        #pragma unroll
        for (int p = 0; p < 4; p++) acc[i][p] = 0ull;

    const ulonglong2* wq = (const ulonglong2*)ws_s;   // [d][4 x ulonglong2]
    const int wbase = hg * 2;
    const int kc0 = r * 9 + dg * 2;
    const int kc1 = (r + 32) * 9 + dg * 2;
    const int kc2 = (r + 64) * 9 + dg * 2;
    const int kc3 = (r + 96) * 9 + dg * 2;

    #pragma unroll
    for (int c = 0; c < 8; c++) {
        cpa_wait<1>();
        __syncthreads();
        if (c + 2 < 8) KS_ISSUE(c + 2);
        cpa_commit();

        const float4* kb = pipe + (c % 3) * 1152;      // constant under unroll
        #pragma unroll
        for (int j = 0; j < 2; j++) {
            float4 kv0 = kb[kc0 + j];
            float4 kv1 = kb[kc1 + j];
            float4 kv2 = kb[kc2 + j];
            float4 kv3 = kb[kc3 + j];
            #pragma unroll
            for (int dl = 0; dl < 4; dl++) {
                const int dd = c * 32 + dg * 8 + j * 4 + dl;   // constant offsets
                ulonglong2 w0 = wq[dd * 4 + wbase];
                ulonglong2 w1 = wq[dd * 4 + wbase + 1];
                float kf0 = ((const float*)&kv0)[dl];
                float kf1 = ((const float*)&kv1)[dl];
                float kf2 = ((const float*)&kv2)[dl];
                float kf3 = ((const float*)&kv3)[dl];
                ull kk0 = pk2(kf0, kf0), kk1 = pk2(kf1, kf1);
                ull kk2 = pk2(kf2, kf2), kk3 = pk2(kf3, kf3);
                acc[0][0] = fma2(kk0, w0.x, acc[0][0]); acc[0][1] = fma2(kk0, w0.y, acc[0][1]);
                acc[0][2] = fma2(kk0, w1.x, acc[0][2]); acc[0][3] = fma2(kk0, w1.y, acc[0][3]);
                acc[1][0] = fma2(kk1, w0.x, acc[1][0]); acc[1][1] = fma2(kk1, w0.y, acc[1][1]);
                acc[1][2] = fma2(kk1, w1.x, acc[1][2]); acc[1][3] = fma2(kk1, w1.y, acc[1][3]);
                acc[2][0] = fma2(kk2, w0.x, acc[2][0]); acc[2][1] = fma2(kk2, w0.y, acc[2][1]);
                acc[2][2] = fma2(kk2, w1.x, acc[2][2]); acc[2][3] = fma2(kk2, w1.y, acc[2][3]);
                acc[3][0] = fma2(kk3, w0.x, acc[3][0]); acc[3][1] = fma2(kk3, w0.y, acc[3][1]);
                acc[3][2] = fma2(kk3, w1.x, acc[3][2]); acc[3][3] = fma2(kk3, w1.y, acc[3][3]);
            }
        }
    }
#undef KS_ISSUE

    // reduce the 4 dg partials via smem (reuse ring region; stride 9 pad)
    __syncthreads();
    ull* sred = (ull*)(sm + 4096);        // 4 * 1152 ull = 36864 B <= 55296 B
    #pragma unroll
    for (int i = 0; i < 4; i++)
        #pragma unroll
        for (int p = 0; p < 4; p++)
            sred[dg * 1152 + (r + 32 * i) * 9 + hg * 4 + p] = acc[i][p];
    __syncthreads();

    const int row = tid >> 1, pb = (tid & 1) * 4;
    const int s = st * 128 + row;
    float* outp = g_scores_part[dq];
    #pragma unroll
    for (int j = 0; j < 4; j++) {
        int p = pb + j;
        ull t = add2(add2(sred[row * 9 + p],        sred[1152 + row * 9 + p]),
                     add2(sred[2304 + row * 9 + p], sred[3456 + row * 9 + p]));
        float lo, hi; upk2(lo, hi, t);
        outp[(size_t)(b * 16 + 2 * p) * 2048 + s]     = lo;
        outp[(size_t)(b * 16 + 2 * p + 1) * 2048 + s] = hi;
    }
}

// softmax over s per (b,h); sums 4 d-partials; write attn[b][s][h]
__global__ __launch_bounds__(256) void k_softmax() {
    int b = blockIdx.x, h = blockIdx.y, tid = threadIdx.x;
    size_t off = (size_t)(b * 16 + h) * 2048;
    float x[8], m = -1e30f;
    #pragma unroll
    for (int i = 0; i < 8; i++) {
        int s = tid + i * 256;
        float v = g_scores_part[0][off + s] + g_scores_part[1][off + s]
                + g_scores_part[2][off + s] + g_scores_part[3][off + s];
        x[i] = v; m = fmaxf(m, v);
    }
    __shared__ float red[8];
    #pragma unroll
    for (int o = 16; o; o >>= 1) m = fmaxf(m, __shfl_xor_sync(0xffffffffu, m, o));
    if ((tid & 31) == 0) red[tid >> 5] = m;
    __syncthreads();
    float M = red[0];
    #pragma unroll
    for (int i = 1; i < 8; i++) M = fmaxf(M, red[i]);
    __syncthreads();
    float ssum = 0.f;
    #pragma unroll
    for (int i = 0; i < 8; i++) { x[i] = __expf(x[i] - M); ssum += x[i]; }
    #pragma unroll
    for (int o = 16; o; o >>= 1) ssum += __shfl_xor_sync(0xffffffffu, ssum, o);
    if ((tid & 31) == 0) red[tid >> 5] = ssum;
    __syncthreads();
    float T = 0.f;
    #pragma unroll
    for (int i = 0; i < 8; i++) T += red[i];
    float inv = 1.0f / T;
    #pragma unroll
    for (int i = 0; i < 8; i++)
        g_attn[((size_t)b * 2048 + tid + i * 256) * 16 + h] = x[i] * inv;
}

// ---------------- pass 2: stream v -> vbar via RED.ADD ----------------
// grid (64 b, 2 dh, 16 sq). CTA: 128 s x 512 d x 16 h; 16 stages of 8 s via
// 4-stage cp.async ring (constants under x4 unroll). Thread (hg=tid>>7,
// dt=tid&127): 4 d x 8 heads x 8 s per stage. 67584 B smem, 3 CTAs/SM.
// Epilogue: atomicAdd into g_vbar (kills the 64MB partial read in gemm1).
__global__ __launch_bounds__(256, 3) void k_vbar(const float* __restrict__ v) {
    extern __shared__ float vsm[];             // 4 stages x 4224 floats
    const int b = blockIdx.x, dh = blockIdx.y, sq = blockIdx.z;
    const int tid = threadIdx.x;
    const int hg = tid >> 7, dt = tid & 127;
    const size_t sBase = (size_t)b * 2048 + sq * 128;
    const float4* vg = (const float4*)v;
    const float4* ag = (const float4*)g_attn;
    const unsigned smb = smem_u32(vsm);

    const int sl0 = tid >> 7;
    const float4* vg0 = vg + (sBase + sl0) * 256 + dh * 128 + (tid & 127);
    const float4* agp = ag + sBase * 4 + tid;
    const unsigned vs_off = (unsigned)tid * 16u;

#define VB_ISSUE(c, stg) do { \
    unsigned sb = smb + (unsigned)((stg) * 16896); \
    _Pragma("unroll") \
    for (int i2 = 0; i2 < 4; i2++) \
        cpa16(sb + vs_off + (unsigned)i2 * 4096u, \
              vg0 + ((size_t)(c) * 8 + i2 * 2) * 256); \
    if (tid < 32) cpa16(sb + 16384u + (unsigned)tid * 16u, agp + (c) * 32); \
} while (0)

    VB_ISSUE(0, 0); cpa_commit();
    VB_ISSUE(1, 1); cpa_commit();
    VB_ISSUE(2, 2); cpa_commit();

    ull acc[4][4];
    #pragma unroll
    for (int d = 0; d < 4; d++)
        #pragma unroll
        for (int hp = 0; hp < 4; hp++) acc[d][hp] = 0ull;

    const int abase = hg * 8;
    for (int cc = 0; cc < 4; cc++) {
        #pragma unroll
        for (int u = 0; u < 4; u++) {
            const int c = cc * 4 + u;
            cpa_wait<2>();
            __syncthreads();
            if (c + 3 < 16) VB_ISSUE(c + 3, (u + 3) & 3);
            cpa_commit();

            const float* stg = vsm + u * 4224;
            const float4* vb4 = (const float4*)stg + dt;
            const float* ab = stg + 4096 + abase;
            #pragma unroll
            for (int sl = 0; sl < 8; sl++) {
                float4 vv = vb4[sl * 128];
                ulonglong2 a01 = *(const ulonglong2*)(ab + sl * 16);
                ulonglong2 a23 = *(const ulonglong2*)(ab + sl * 16 + 4);
                ull v0 = pk2(vv.x, vv.x), v1 = pk2(vv.y, vv.y);
                ull v2 = pk2(vv.z, vv.z), v3 = pk2(vv.w, vv.w);
                acc[0][0] = fma2(a01.x, v0, acc[0][0]); acc[1][0] = fma2(a01.x, v1, acc[1][0]);
                acc[2][0] = fma2(a01.x, v2, acc[2][0]); acc[3][0] = fma2(a01.x, v3, acc[3][0]);
                acc[0][1] = fma2(a01.y, v0, acc[0][1]); acc[1][1] = fma2(a01.y, v1, acc[1][1]);
                acc[2][1] = fma2(a01.y, v2, acc[2][1]); acc[3][1] = fma2(a01.y, v3, acc[3][1]);
                acc[0][2] = fma2(a23.x, v0, acc[0][2]); acc[1][2] = fma2(a23.x, v1, acc[1][2]);
                acc[2][2] = fma2(a23.x, v2, acc[2][2]); acc[3][2] = fma2(a23.x, v3, acc[3][2]);
                acc[0][3] = fma2(a23.y, v0, acc[0][3]); acc[1][3] = fma2(a23.y, v1, acc[1][3]);
                acc[2][3] = fma2(a23.y, v2, acc[2][3]); acc[3][3] = fma2(a23.y, v3, acc[3][3]);
            }
        }
    }
#undef VB_ISSUE

    // epilogue: RED.ADD into single g_vbar buffer (16 sq CTAs per address)
    float* outb = g_vbar + (size_t)b * 16384;
    const int d0 = dh * 512 + dt * 4;
    #pragma unroll
    for (int hp = 0; hp < 4; hp++) {
        float lo0, hi0, lo1, hi1, lo2, hi2, lo3, hi3;
        upk2(lo0, hi0, acc[0][hp]); upk2(lo1, hi1, acc[1][hp]);
        upk2(lo2, hi2, acc[2][hp]); upk2(lo3, hi3, acc[3][hp]);
        int h0 = hg * 8 + 2 * hp;
        float* pe = outb + (size_t)h0 * 1024 + d0;
        float* po = pe + 1024;
        atomicAdd(pe + 0, lo0); atomicAdd(pe + 1, lo1);
        atomicAdd(pe + 2, lo2); atomicAdd(pe + 3, lo3);
        atomicAdd(po + 0, hi0); atomicAdd(po + 1, hi1);
        atomicAdd(po + 2, hi2); atomicAdd(po + 3, hi3);
    }
}

__global__ __launch_bounds__(256) void k_relu(float* __restrict__ out) {
    int i = blockIdx.x * 256 + threadIdx.x;
    out[i] = fmaxf(g_outpre[i], 0.0f);
}

extern "C" void kernel_launch(void* const* d_in, const int* in_sizes, int n_in,
                              void* d_out, int out_size) {
    const float* q  = (const float*)d_in[0];
    const float* k  = (const float*)d_in[1];
    const float* v  = (const float*)d_in[2];
    const float* Wq = (const float*)d_in[3];
    const float* bq = (const float*)d_in[4];
    const float* Wk = (const float*)d_in[5];
    // d_in[6] = bk — cancels in softmax
    const float* Wv = (const float*)d_in[7];
    const float* bv = (const float*)d_in[8];
    const float* Wo = (const float*)d_in[9];
    const float* bo = (const float*)d_in[10];

    const int smem_scores = 4096 * 4 + 3 * 1152 * 16;  // 71680
    const int smem_vbar   = 4 * 16896;                 // 67584
    static bool attr_done = false;
    if (!attr_done) {
        cudaFuncSetAttribute(k_scores, cudaFuncAttributeMaxDynamicSharedMemorySize, smem_scores);
        cudaFuncSetAttribute(k_vbar,   cudaFuncAttributeMaxDynamicSharedMemorySize, smem_vbar);
        attr_done = true;
    }

    k_init<<<256, 256>>>(bq, bv, bo);
    gemm_ksplit<<<dim3(16, 16), 256>>>(q, Wq, 0);
    k_ws<<<dim3(16, 8, 4), 256>>>(Wk);
    k_scores<<<dim3(64, 16, 4), 256, smem_scores>>>(k);
    k_softmax<<<dim3(64, 16), 256>>>();
    k_vbar<<<dim3(64, 2, 16), 256, smem_vbar>>>(v);
    gemm_ksplit<<<dim3(16, 16), 256>>>(nullptr, Wv, 1);
    gemm_ksplit<<<dim3(16, 16), 256>>>(nullptr, Wo, 2);
    k_relu<<<256, 256>>>((float*)d_out);
}

// round 17
// speedup vs baseline: 1.0230x; 1.0230x over previous
#include <cuda_runtime.h>
#include <cstdint>
#include <cstddef>

typedef unsigned long long ull;

// device scratch (allocs forbidden)
__device__ float g_qh[64 * 1024];
__device__ float g_ws[64 * 1024 * 16];                 // [b][d][h]
__device__ float g_scores_part[2][64 * 16 * 2048];     // [dq][b][h][s]
__device__ float g_attn[64 * 2048 * 16];               // [b][s][h]
__device__ float g_vbar_part[16][64 * 16 * 1024];      // [sq][b][h][d]
__device__ float g_concat[64 * 1024];
__device__ float g_outpre[64 * 1024];

__device__ __forceinline__ ull pk2(float x, float y) {
    ull r; asm("mov.b64 %0, {%1,%2};" : "=l"(r) : "f"(x), "f"(y)); return r;
}
__device__ __forceinline__ void upk2(float& x, float& y, ull v) {
    asm("mov.b64 {%0,%1}, %2;" : "=f"(x), "=f"(y) : "l"(v));
}
__device__ __forceinline__ ull fma2(ull a, ull b, ull c) {
    ull d; asm("fma.rn.f32x2 %0, %1, %2, %3;" : "=l"(d) : "l"(a), "l"(b), "l"(c)); return d;
}
__device__ __forceinline__ ull add2(ull a, ull b) {
    ull c; asm("add.rn.f32x2 %0, %1, %2;" : "=l"(c) : "l"(a), "l"(b)); return c;
}
__device__ __forceinline__ unsigned smem_u32(const void* p) {
    return (unsigned)__cvta_generic_to_shared(p);
}
__device__ __forceinline__ void cpa16(unsigned s, const void* g) {
    asm volatile("cp.async.cg.shared.global [%0], [%1], 16;" :: "r"(s), "l"(g));
}
__device__ __forceinline__ void cpa_commit() {
    asm volatile("cp.async.commit_group;" ::: "memory");
}
template <int N> __device__ __forceinline__ void cpa_wait() {
    asm volatile("cp.async.wait_group %0;" :: "n"(N) : "memory");
}

__global__ __launch_bounds__(256) void k_init(const float* __restrict__ bq,
                                              const float* __restrict__ bv,
                                              const float* __restrict__ bo) {
    int i = blockIdx.x * 256 + threadIdx.x;
    int c = i & 1023;
    g_qh[i] = bq[c]; g_concat[i] = bv[c]; g_outpre[i] = bo[c];
}

// C[64,1024] += A[64,1024] @ W[1024,1024]; 16-way k-split over by, 64-col tiles over bx.
// mode 0: A=q -> g_qh | mode 1: A=sum of 16 vbar partials (head h=bx) -> g_concat
// mode 2: A=g_concat -> g_outpre
__global__ __launch_bounds__(256) void gemm_ksplit(const float* __restrict__ Ain,
                                                   const float* __restrict__ W, int mode) {
    __shared__ float As[64 * 68];
    __shared__ float Wsm[64 * 64];
    int bx = blockIdx.x, by = blockIdx.y, tid = threadIdx.x;
    int col0 = bx * 64, db = by * 64;

    if (mode == 1) {
        for (int idx = tid; idx < 4096; idx += 256) {
            int bb = idx >> 6, dd = idx & 63;
            size_t off = (size_t)bb * 16384 + (size_t)bx * 1024 + db + dd;
            float s = 0.f;
            #pragma unroll
            for (int p = 0; p < 16; p++) s += g_vbar_part[p][off];
            As[bb * 68 + dd] = s;
        }
    } else {
        const float* A = (mode == 0) ? Ain : g_concat;
        for (int idx = tid; idx < 4096; idx += 256) {
            int bb = idx >> 6, dd = idx & 63;
            As[bb * 68 + dd] = A[(size_t)bb * 1024 + db + dd];
        }
    }
    for (int idx = tid; idx < 4096; idx += 256) {
        int dd = idx >> 6, j = idx & 63;
        Wsm[dd * 64 + j] = W[(size_t)(db + dd) * 1024 + col0 + j];
    }
    __syncthreads();

    int tj = tid & 15, tb = tid >> 4;
    float acc[4][4] = {};
    const float4* Ws4 = (const float4*)Wsm;
    #pragma unroll 8
    for (int dd = 0; dd < 64; dd++) {
        float4 w = Ws4[dd * 16 + tj];
        #pragma unroll
        for (int bb = 0; bb < 4; bb++) {
            float a = As[(tb * 4 + bb) * 68 + dd];
            acc[bb][0] = fmaf(a, w.x, acc[bb][0]);
            acc[bb][1] = fmaf(a, w.y, acc[bb][1]);
            acc[bb][2] = fmaf(a, w.z, acc[bb][2]);
            acc[bb][3] = fmaf(a, w.w, acc[bb][3]);
        }
    }
    float* C = (mode == 0) ? g_qh : (mode == 1) ? g_concat : g_outpre;
    #pragma unroll
    for (int bb = 0; bb < 4; bb++)
        #pragma unroll
        for (int jj = 0; jj < 4; jj++)
            atomicAdd(&C[(size_t)(tb * 4 + bb) * 1024 + col0 + tj * 4 + jj], acc[bb][jj]);
}

// g_ws[b][d][h] = 0.125 * sum_j Wk[d, 64h+j] * g_qh[b, 64h+j]; grid (16 dt, 8 bt, 4 hz)
__global__ __launch_bounds__(256) void k_ws(const float* __restrict__ Wk) {
    __shared__ float Wks[64 * 68];
    __shared__ float qhs[8 * 64];
    int dt = blockIdx.x, bt = blockIdx.y, hz = blockIdx.z, tid = threadIdx.x;
    int td = tid & 63, tg = tid >> 6;
    for (int hi = 0; hi < 4; hi++) {
        int h = hz * 4 + hi;
        __syncthreads();
        for (int idx = tid; idx < 4096; idx += 256) {
            int dd = idx >> 6, j = idx & 63;
            Wks[dd * 68 + j] = Wk[(size_t)(dt * 64 + dd) * 1024 + h * 64 + j];
        }
        for (int idx = tid; idx < 512; idx += 256) {
            int bb = idx >> 6, j = idx & 63;
            qhs[bb * 64 + j] = g_qh[(size_t)(bt * 8 + bb) * 1024 + h * 64 + j];
        }
        __syncthreads();
        float a0 = 0.f, a1 = 0.f;
        #pragma unroll
        for (int j4 = 0; j4 < 16; j4++) {
            float4 w  = *(const float4*)&Wks[td * 68 + j4 * 4];
            float4 qa = *(const float4*)&qhs[(tg * 2 + 0) * 64 + j4 * 4];
            float4 qb = *(const float4*)&qhs[(tg * 2 + 1) * 64 + j4 * 4];
            a0 = fmaf(w.x, qa.x, fmaf(w.y, qa.y, fmaf(w.z, qa.z, fmaf(w.w, qa.w, a0))));
            a1 = fmaf(w.x, qb.x, fmaf(w.y, qb.y, fmaf(w.z, qb.z, fmaf(w.w, qb.w, a1))));
        }
        int d = dt * 64 + td;
        g_ws[((size_t)(bt * 8 + tg * 2 + 0) * 1024 + d) * 16 + h] = a0 * 0.125f;
        g_ws[((size_t)(bt * 8 + tg * 2 + 1) * 1024 + d) * 16 + h] = a1 * 0.125f;
    }
}

// ---------------- pass 1: stream k -> partial scores ----------------
// grid (64 b, 16 st, 2 dq). CTA tile: 128 s x 512 d, 16 chunks of 32 d.
// 3-stage cp.async ring (stage = [128 rows][9 f4]), fully unrolled; ws_s
// holds 256 d x 16 h and is RELOADED at the half-way chunk (c==8).
// Thread (hg=tid>>7, dg=(tid>>5)&3, r=tid&31): 4 rows, 8 heads, 8 d/chunk.
// dyn smem = 16384 + 3*18432 = 71680 B; 3 CTAs/SM. Partial slots: 2 (was 4).
__global__ __launch_bounds__(256, 3) void k_scores(const float* __restrict__ k) {
    extern __shared__ float sm[];
    float* ws_s = sm;                          // 4096 f: [256 d][16 h] (per half)
    float4* pipe = (float4*)(sm + 4096);       // 3 stages x 1152 f4
    const int b = blockIdx.x, st = blockIdx.y, dq = blockIdx.z;
    const int tid = threadIdx.x;
    const int r = tid & 31;
    const int dg = (tid >> 5) & 3;
    const int hg = tid >> 7;

    const float4* wsrc = (const float4*)(g_ws + (size_t)b * 16384 + dq * 8192);
    {   // stage ws slice for half 0 (coalesced)
        float4* dst = (float4*)ws_s;
        #pragma unroll
        for (int i = 0; i < 4; i++) dst[tid + i * 256] = wsrc[tid + i * 256];
    }

    const float4* k4 = (const float4*)k;
    const size_t gbase = ((size_t)b * 2048 + st * 128) * 256 + dq * 128;  // f4 units
    const int row0 = tid >> 3, col0 = tid & 7;
    const float4* kg = k4 + gbase + (size_t)row0 * 256 + col0;
    const unsigned sbase = smem_u32(pipe);
    const unsigned soff = sbase + (unsigned)(row0 * 9 + col0) * 16u;

#define KS_ISSUE(c) do { \
    unsigned sb = soff + (unsigned)(((c) % 3) * 1152) * 16u; \
    _Pragma("unroll") \
    for (int i = 0; i < 4; i++) \
        cpa16(sb + (unsigned)i * (32u * 9u * 16u), \
              kg + (size_t)i * 32 * 256 + (c) * 8); \
} while (0)

    KS_ISSUE(0); cpa_commit();
    KS_ISSUE(1); cpa_commit();

    ull acc[4][4];   // [row i][h-pair p within hg]
    #pragma unroll
    for (int i = 0; i < 4; i++)
        #pragma unroll
        for (int p = 0; p < 4; p++) acc[i][p] = 0ull;

    const ulonglong2* wq = (const ulonglong2*)ws_s;   // [d_local][4 x ulonglong2]
    const int wbase = hg * 2;
    const int kc0 = r * 9 + dg * 2;
    const int kc1 = (r + 32) * 9 + dg * 2;
    const int kc2 = (r + 64) * 9 + dg * 2;
    const int kc3 = (r + 96) * 9 + dg * 2;

    #pragma unroll
    for (int c = 0; c < 16; c++) {
        cpa_wait<1>();
        __syncthreads();
        if (c == 8) {   // reload ws slice for half 1 (all threads past half-0 reads)
            float4* dst = (float4*)ws_s;
            #pragma unroll
            for (int i = 0; i < 4; i++)
                dst[tid + i * 256] = wsrc[1024 + tid + i * 256];
            __syncthreads();
        }
        if (c + 2 < 16) KS_ISSUE(c + 2);
        cpa_commit();

        const float4* kb = pipe + (c % 3) * 1152;      // constant under unroll
        #pragma unroll
        for (int j = 0; j < 2; j++) {
            float4 kv0 = kb[kc0 + j];
            float4 kv1 = kb[kc1 + j];
            float4 kv2 = kb[kc2 + j];
            float4 kv3 = kb[kc3 + j];
            #pragma unroll
            for (int dl = 0; dl < 4; dl++) {
                const int dd = (c & 7) * 32 + dg * 8 + j * 4 + dl;  // local d, constant
                ulonglong2 w0 = wq[dd * 4 + wbase];
                ulonglong2 w1 = wq[dd * 4 + wbase + 1];
                float kf0 = ((const float*)&kv0)[dl];
                float kf1 = ((const float*)&kv1)[dl];
                float kf2 = ((const float*)&kv2)[dl];
                float kf3 = ((const float*)&kv3)[dl];
                ull kk0 = pk2(kf0, kf0), kk1 = pk2(kf1, kf1);
                ull kk2 = pk2(kf2, kf2), kk3 = pk2(kf3, kf3);
                acc[0][0] = fma2(kk0, w0.x, acc[0][0]); acc[0][1] = fma2(kk0, w0.y, acc[0][1]);
                acc[0][2] = fma2(kk0, w1.x, acc[0][2]); acc[0][3] = fma2(kk0, w1.y, acc[0][3]);
                acc[1][0] = fma2(kk1, w0.x, acc[1][0]); acc[1][1] = fma2(kk1, w0.y, acc[1][1]);
                acc[1][2] = fma2(kk1, w1.x, acc[1][2]); acc[1][3] = fma2(kk1, w1.y, acc[1][3]);
                acc[2][0] = fma2(kk2, w0.x, acc[2][0]); acc[2][1] = fma2(kk2, w0.y, acc[2][1]);
                acc[2][2] = fma2(kk2, w1.x, acc[2][2]); acc[2][3] = fma2(kk2, w1.y, acc[2][3]);
                acc[3][0] = fma2(kk3, w0.x, acc[3][0]); acc[3][1] = fma2(kk3, w0.y, acc[3][1]);
                acc[3][2] = fma2(kk3, w1.x, acc[3][2]); acc[3][3] = fma2(kk3, w1.y, acc[3][3]);
            }
        }
    }
#undef KS_ISSUE

    // reduce the 4 dg partials via smem (reuse ring region; stride 9 pad)
    __syncthreads();
    ull* sred = (ull*)(sm + 4096);        // 4 * 1152 ull = 36864 B <= 55296 B
    #pragma unroll
    for (int i = 0; i < 4; i++)
        #pragma unroll
        for (int p = 0; p < 4; p++)
            sred[dg * 1152 + (r + 32 * i) * 9 + hg * 4 + p] = acc[i][p];
    __syncthreads();

    const int row = tid >> 1, pb = (tid & 1) * 4;
    const int s = st * 128 + row;
    float* outp = g_scores_part[dq];
    #pragma unroll
    for (int j = 0; j < 4; j++) {
        int p = pb + j;
        ull t = add2(add2(sred[row * 9 + p],        sred[1152 + row * 9 + p]),
                     add2(sred[2304 + row * 9 + p], sred[3456 + row * 9 + p]));
        float lo, hi; upk2(lo, hi, t);
        outp[(size_t)(b * 16 + 2 * p) * 2048 + s]     = lo;
        outp[(size_t)(b * 16 + 2 * p + 1) * 2048 + s] = hi;
    }
}

// softmax over s per (b,h); sums 2 d-partials; write attn[b][s][h]
__global__ __launch_bounds__(256) void k_softmax() {
    int b = blockIdx.x, h = blockIdx.y, tid = threadIdx.x;
    size_t off = (size_t)(b * 16 + h) * 2048;
    float x[8], m = -1e30f;
    #pragma unroll
    for (int i = 0; i < 8; i++) {
        int s = tid + i * 256;
        float v = g_scores_part[0][off + s] + g_scores_part[1][off + s];
        x[i] = v; m = fmaxf(m, v);
    }
    __shared__ float red[8];
    #pragma unroll
    for (int o = 16; o; o >>= 1) m = fmaxf(m, __shfl_xor_sync(0xffffffffu, m, o));
    if ((tid & 31) == 0) red[tid >> 5] = m;
    __syncthreads();
    float M = red[0];
    #pragma unroll
    for (int i = 1; i < 8; i++) M = fmaxf(M, red[i]);
    __syncthreads();
    float ssum = 0.f;
    #pragma unroll
    for (int i = 0; i < 8; i++) { x[i] = __expf(x[i] - M); ssum += x[i]; }
    #pragma unroll
    for (int o = 16; o; o >>= 1) ssum += __shfl_xor_sync(0xffffffffu, ssum, o);
    if ((tid & 31) == 0) red[tid >> 5] = ssum;
    __syncthreads();
    float T = 0.f;
    #pragma unroll
    for (int i = 0; i < 8; i++) T += red[i];
    float inv = 1.0f / T;
    #pragma unroll
    for (int i = 0; i < 8; i++)
        g_attn[((size_t)b * 2048 + tid + i * 256) * 16 + h] = x[i] * inv;
}

// ---------------- pass 2: stream v -> partial vbar ----------------
// grid (64 b, 2 dh, 16 sq). CTA: 128 s x 512 d x 16 h; 16 stages of 8 s via
// 4-stage cp.async ring (constants under x4 unroll). Thread (hg=tid>>7,
// dt=tid&127): 4 d x 8 heads x 8 s per stage. 67584 B smem, 3 CTAs/SM.
// (R13-exact config — best measured.)
__global__ __launch_bounds__(256, 3) void k_vbar(const float* __restrict__ v) {
    extern __shared__ float vsm[];             // 4 stages x 4224 floats
    const int b = blockIdx.x, dh = blockIdx.y, sq = blockIdx.z;
    const int tid = threadIdx.x;
    const int hg = tid >> 7, dt = tid & 127;
    const size_t sBase = (size_t)b * 2048 + sq * 128;
    const float4* vg = (const float4*)v;
    const float4* ag = (const float4*)g_attn;
    const unsigned smb = smem_u32(vsm);

    const int sl0 = tid >> 7;
    const float4* vg0 = vg + (sBase + sl0) * 256 + dh * 128 + (tid & 127);
    const float4* agp = ag + sBase * 4 + tid;
    const unsigned vs_off = (unsigned)tid * 16u;

#define VB_ISSUE(c, stg) do { \
    unsigned sb = smb + (unsigned)((stg) * 16896); \
    _Pragma("unroll") \
    for (int i2 = 0; i2 < 4; i2++) \
        cpa16(sb + vs_off + (unsigned)i2 * 4096u, \
              vg0 + ((size_t)(c) * 8 + i2 * 2) * 256); \
    if (tid < 32) cpa16(sb + 16384u + (unsigned)tid * 16u, agp + (c) * 32); \
} while (0)

    VB_ISSUE(0, 0); cpa_commit();
    VB_ISSUE(1, 1); cpa_commit();
    VB_ISSUE(2, 2); cpa_commit();

    ull acc[4][4];
    #pragma unroll
    for (int d = 0; d < 4; d++)
        #pragma unroll
        for (int hp = 0; hp < 4; hp++) acc[d][hp] = 0ull;

    const int abase = hg * 8;
    for (int cc = 0; cc < 4; cc++) {
        #pragma unroll
        for (int u = 0; u < 4; u++) {
            const int c = cc * 4 + u;
            cpa_wait<2>();
            __syncthreads();
            if (c + 3 < 16) VB_ISSUE(c + 3, (u + 3) & 3);
            cpa_commit();

            const float* stg = vsm + u * 4224;
            const float4* vb4 = (const float4*)stg + dt;
            const float* ab = stg + 4096 + abase;
            #pragma unroll
            for (int sl = 0; sl < 8; sl++) {
                float4 vv = vb4[sl * 128];
                ulonglong2 a01 = *(const ulonglong2*)(ab + sl * 16);
                ulonglong2 a23 = *(const ulonglong2*)(ab + sl * 16 + 4);
                ull v0 = pk2(vv.x, vv.x), v1 = pk2(vv.y, vv.y);
                ull v2 = pk2(vv.z, vv.z), v3 = pk2(vv.w, vv.w);
                acc[0][0] = fma2(a01.x, v0, acc[0][0]); acc[1][0] = fma2(a01.x, v1, acc[1][0]);
                acc[2][0] = fma2(a01.x, v2, acc[2][0]); acc[3][0] = fma2(a01.x, v3, acc[3][0]);
                acc[0][1] = fma2(a01.y, v0, acc[0][1]); acc[1][1] = fma2(a01.y, v1, acc[1][1]);
                acc[2][1] = fma2(a01.y, v2, acc[2][1]); acc[3][1] = fma2(a01.y, v3, acc[3][1]);
                acc[0][2] = fma2(a23.x, v0, acc[0][2]); acc[1][2] = fma2(a23.x, v1, acc[1][2]);
                acc[2][2] = fma2(a23.x, v2, acc[2][2]); acc[3][2] = fma2(a23.x, v3, acc[3][2]);
                acc[0][3] = fma2(a23.y, v0, acc[0][3]); acc[1][3] = fma2(a23.y, v1, acc[1][3]);
                acc[2][3] = fma2(a23.y, v2, acc[2][3]); acc[3][3] = fma2(a23.y, v3, acc[3][3]);
            }
        }
    }
#undef VB_ISSUE

    float* outp = g_vbar_part[sq] + (size_t)b * 16384;
    const int d0 = dh * 512 + dt * 4;
    #pragma unroll
    for (int hp = 0; hp < 4; hp++) {
        float lo0, hi0, lo1, hi1, lo2, hi2, lo3, hi3;
        upk2(lo0, hi0, acc[0][hp]); upk2(lo1, hi1, acc[1][hp]);
        upk2(lo2, hi2, acc[2][hp]); upk2(lo3, hi3, acc[3][hp]);
        float4 e; e.x = lo0; e.y = lo1; e.z = lo2; e.w = lo3;
        float4 o; o.x = hi0; o.y = hi1; o.z = hi2; o.w = hi3;
        int h0 = hg * 8 + 2 * hp;
        *(float4*)&outp[(size_t)h0 * 1024 + d0]       = e;
        *(float4*)&outp[(size_t)(h0 + 1) * 1024 + d0] = o;
    }
}

__global__ __launch_bounds__(256) void k_relu(float* __restrict__ out) {
    int i = blockIdx.x * 256 + threadIdx.x;
    out[i] = fmaxf(g_outpre[i], 0.0f);
}

extern "C" void kernel_launch(void* const* d_in, const int* in_sizes, int n_in,
                              void* d_out, int out_size) {
    const float* q  = (const float*)d_in[0];
    const float* k  = (const float*)d_in[1];
    const float* v  = (const float*)d_in[2];
    const float* Wq = (const float*)d_in[3];
    const float* bq = (const float*)d_in[4];
    const float* Wk = (const float*)d_in[5];
    // d_in[6] = bk — cancels in softmax
    const float* Wv = (const float*)d_in[7];
    const float* bv = (const float*)d_in[8];
    const float* Wo = (const float*)d_in[9];
    const float* bo = (const float*)d_in[10];

    const int smem_scores = 4096 * 4 + 3 * 1152 * 16;  // 71680
    const int smem_vbar   = 4 * 16896;                 // 67584
    static bool attr_done = false;
    if (!attr_done) {
        cudaFuncSetAttribute(k_scores, cudaFuncAttributeMaxDynamicSharedMemorySize, smem_scores);
        cudaFuncSetAttribute(k_vbar,   cudaFuncAttributeMaxDynamicSharedMemorySize, smem_vbar);
        attr_done = true;
    }

    k_init<<<256, 256>>>(bq, bv, bo);
    gemm_ksplit<<<dim3(16, 16), 256>>>(q, Wq, 0);
    k_ws<<<dim3(16, 8, 4), 256>>>(Wk);
    k_scores<<<dim3(64, 16, 2), 256, smem_scores>>>(k);
    k_softmax<<<dim3(64, 16), 256>>>();
    k_vbar<<<dim3(64, 2, 16), 256, smem_vbar>>>(v);
    gemm_ksplit<<<dim3(16, 16), 256>>>(nullptr, Wv, 1);
    gemm_ksplit<<<dim3(16, 16), 256>>>(nullptr, Wo, 2);
    k_relu<<<256, 256>>>((float*)d_out);
}